// round 3
// baseline (speedup 1.0000x reference)
#include <cuda_runtime.h>
#include <cuda_bf16.h>
#include <math.h>

// Problem constants
#define BATCH   2
#define T_SEQ   2048
#define CDIM    1024
#define NH      16
#define DH      64
#define C3      (3 * CDIM)

// Scratch (device globals — no cudaMalloc allowed)
__device__ float g_qkv[(size_t)BATCH * T_SEQ * C3];   // [B, T, 3C]  (48 MB)
__device__ float g_attn[(size_t)BATCH * T_SEQ * CDIM]; // [B, T, C]  (32 MB)

// ---------------------------------------------------------------------------
// SGEMM: C[M,N] = A[M,K] @ B[K,N] + bias[N]
// BM=BN=128, BK=8, 256 threads, 8x8 microtile. M%128==0, N%128==0, K%8==0.
// ---------------------------------------------------------------------------
__global__ __launch_bounds__(256, 2)
void sgemm_bias_kernel(const float* __restrict__ A, const float* __restrict__ B,
                       const float* __restrict__ bias, float* __restrict__ C,
                       int M, int N, int K) {
    __shared__ float As[8][128];
    __shared__ float Bs[8][128];

    const int tid = threadIdx.x;
    const int tx = tid & 15;        // 0..15  -> col group
    const int ty = tid >> 4;        // 0..15  -> row group
    const int row0 = blockIdx.y * 128;
    const int col0 = blockIdx.x * 128;

    // A tile: 128 rows x 8 cols -> one float4 per thread
    const int arow = tid >> 1;            // 0..127
    const int ak   = (tid & 1) * 4;       // 0 or 4
    // B tile: 8 rows x 128 cols -> one float4 per thread
    const int brow = tid >> 5;            // 0..7
    const int bcol = (tid & 31) * 4;      // 0..124

    float acc[8][8];
#pragma unroll
    for (int i = 0; i < 8; i++)
#pragma unroll
        for (int j = 0; j < 8; j++) acc[i][j] = 0.f;

    for (int k0 = 0; k0 < K; k0 += 8) {
        float4 av = *(const float4*)&A[(size_t)(row0 + arow) * K + k0 + ak];
        float4 bv = *(const float4*)&B[(size_t)(k0 + brow) * N + col0 + bcol];
        __syncthreads();   // previous iteration's reads done
        As[ak + 0][arow] = av.x;
        As[ak + 1][arow] = av.y;
        As[ak + 2][arow] = av.z;
        As[ak + 3][arow] = av.w;
        *(float4*)&Bs[brow][bcol] = bv;
        __syncthreads();

#pragma unroll
        for (int k = 0; k < 8; k++) {
            float4 a0 = *(const float4*)&As[k][ty * 8];
            float4 a1 = *(const float4*)&As[k][ty * 8 + 4];
            float4 b0 = *(const float4*)&Bs[k][tx * 8];
            float4 b1 = *(const float4*)&Bs[k][tx * 8 + 4];
            float a[8] = {a0.x, a0.y, a0.z, a0.w, a1.x, a1.y, a1.z, a1.w};
            float b[8] = {b0.x, b0.y, b0.z, b0.w, b1.x, b1.y, b1.z, b1.w};
#pragma unroll
            for (int i = 0; i < 8; i++)
#pragma unroll
                for (int j = 0; j < 8; j++) acc[i][j] += a[i] * b[j];
        }
    }

#pragma unroll
    for (int i = 0; i < 8; i++) {
        int r = row0 + ty * 8 + i;
#pragma unroll
        for (int j = 0; j < 8; j++) {
            int c = col0 + tx * 8 + j;
            C[(size_t)r * N + c] = acc[i][j] + bias[c];
        }
    }
}

// ---------------------------------------------------------------------------
// Flash attention (fp32, causal). One block = 64 queries of one (b,h).
// 256 threads, 16x16 grid, 4x4 microtiles. Online softmax.
// Dynamic smem: Qs/Ks/Vs/Ps each 64x65 floats.
// ---------------------------------------------------------------------------
#define AT_PAD 65

__global__ __launch_bounds__(256, 2)
void flash_attn_kernel(const float* __restrict__ qkv, float* __restrict__ out) {
    extern __shared__ float sm[];
    float* Qs = sm;                  // 64*65
    float* Ks = Qs + 64 * AT_PAD;    // 64*65
    float* Vs = Ks + 64 * AT_PAD;    // 64*65
    float* Ps = Vs + 64 * AT_PAD;    // 64*65
    __shared__ float m_s[64], l_s[64], alpha_s[64];

    const int tid = threadIdx.x;
    const int tx = tid & 15;
    const int ty = tid >> 4;
    const int bh = blockIdx.y;
    const int b  = bh >> 4;
    const int h  = bh & 15;
    const int q0 = blockIdx.x * 64;

    const float scale = 0.125f;  // 1/sqrt(64)
    const float* base = qkv + (size_t)b * T_SEQ * C3 + h * DH;

    // Load Q tile (pre-scaled)
    for (int i = tid; i < 64 * DH; i += 256) {
        int r = i >> 6, d = i & 63;
        Qs[r * AT_PAD + d] = base[(size_t)(q0 + r) * C3 + d] * scale;
    }
    if (tid < 64) { m_s[tid] = -INFINITY; l_s[tid] = 0.f; }

    float o[4][4];
#pragma unroll
    for (int i = 0; i < 4; i++)
#pragma unroll
        for (int j = 0; j < 4; j++) o[i][j] = 0.f;

    const int ntiles = q0 / 64 + 1;
    for (int kt = 0; kt < ntiles; kt++) {
        const int k0 = kt * 64;
        __syncthreads();  // K/V reuse; also covers Q-load on first iter
        for (int i = tid; i < 64 * DH; i += 256) {
            int r = i >> 6, d = i & 63;
            size_t gr = (size_t)(k0 + r) * C3;
            Ks[r * AT_PAD + d] = base[gr + CDIM + d];
            Vs[r * AT_PAD + d] = base[gr + 2 * CDIM + d];
        }
        __syncthreads();

        // S = Q K^T (4x4 per thread)
        float s[4][4];
#pragma unroll
        for (int i = 0; i < 4; i++)
#pragma unroll
            for (int j = 0; j < 4; j++) s[i][j] = 0.f;
        for (int d = 0; d < DH; d++) {
            float a[4], kk[4];
#pragma unroll
            for (int i = 0; i < 4; i++) a[i] = Qs[(ty * 4 + i) * AT_PAD + d];
#pragma unroll
            for (int j = 0; j < 4; j++) kk[j] = Ks[(tx * 4 + j) * AT_PAD + d];
#pragma unroll
            for (int i = 0; i < 4; i++)
#pragma unroll
                for (int j = 0; j < 4; j++) s[i][j] += a[i] * kk[j];
        }
        // Causal mask on the diagonal tile
        if (k0 == q0) {
#pragma unroll
            for (int i = 0; i < 4; i++)
#pragma unroll
                for (int j = 0; j < 4; j++)
                    if (tx * 4 + j > ty * 4 + i) s[i][j] = -INFINITY;
        }
#pragma unroll
        for (int i = 0; i < 4; i++)
#pragma unroll
            for (int j = 0; j < 4; j++)
                Ps[(ty * 4 + i) * AT_PAD + tx * 4 + j] = s[i][j];
        __syncthreads();

        // Online-softmax row update (one thread per row)
        if (tid < 64) {
            const int r = tid;
            float m_old = m_s[r];
            float mx = m_old;
            for (int c = 0; c < 64; c++) mx = fmaxf(mx, Ps[r * AT_PAD + c]);
            float sum = 0.f;
            for (int c = 0; c < 64; c++) {
                float p = __expf(Ps[r * AT_PAD + c] - mx);
                Ps[r * AT_PAD + c] = p;
                sum += p;
            }
            float alpha = __expf(m_old - mx);
            l_s[r] = l_s[r] * alpha + sum;
            m_s[r] = mx;
            alpha_s[r] = alpha;
        }
        __syncthreads();

        // O = O*alpha + P @ V
        float al[4];
#pragma unroll
        for (int i = 0; i < 4; i++) al[i] = alpha_s[ty * 4 + i];
#pragma unroll
        for (int i = 0; i < 4; i++)
#pragma unroll
            for (int j = 0; j < 4; j++) o[i][j] *= al[i];
        for (int k = 0; k < 64; k++) {
            float p[4], v[4];
#pragma unroll
            for (int i = 0; i < 4; i++) p[i] = Ps[(ty * 4 + i) * AT_PAD + k];
#pragma unroll
            for (int j = 0; j < 4; j++) v[j] = Vs[k * AT_PAD + tx * 4 + j];
#pragma unroll
            for (int i = 0; i < 4; i++)
#pragma unroll
                for (int j = 0; j < 4; j++) o[i][j] += p[i] * v[j];
        }
    }

    // Normalize + store: out[b, q0+r, h*64 + c]
#pragma unroll
    for (int i = 0; i < 4; i++) {
        float inv = 1.f / l_s[ty * 4 + i];
        size_t row = ((size_t)b * T_SEQ + q0 + ty * 4 + i) * CDIM + h * DH;
#pragma unroll
        for (int j = 0; j < 4; j++)
            out[row + tx * 4 + j] = o[i][j] * inv;
    }
}

// ---------------------------------------------------------------------------
// Launch
// ---------------------------------------------------------------------------
extern "C" void kernel_launch(void* const* d_in, const int* in_sizes, int n_in,
                              void* d_out, int out_size) {
    const float* x      = (const float*)d_in[0];  // [2,2048,1024]
    const float* w_qkv  = (const float*)d_in[1];  // [1024,3072]
    const float* b_qkv  = (const float*)d_in[2];  // [3072]
    const float* w_proj = (const float*)d_in[3];  // [1024,1024]
    const float* b_proj = (const float*)d_in[4];  // [1024]
    float* out = (float*)d_out;                   // [2,2048,1024]

    float* qkv_buf = nullptr;
    float* attn_buf = nullptr;
    cudaGetSymbolAddress((void**)&qkv_buf, g_qkv);
    cudaGetSymbolAddress((void**)&attn_buf, g_attn);

    const int M = BATCH * T_SEQ;   // 4096

    // 1) QKV projection: [4096,1024] @ [1024,3072] + b
    {
        dim3 grid(C3 / 128, M / 128);  // (24, 32)
        sgemm_bias_kernel<<<grid, 256>>>(x, w_qkv, b_qkv, qkv_buf, M, C3, CDIM);
    }

    // 2) Flash attention
    {
        int smem = 4 * 64 * AT_PAD * (int)sizeof(float);  // 66560 B
        cudaFuncSetAttribute(flash_attn_kernel,
                             cudaFuncAttributeMaxDynamicSharedMemorySize, smem);
        dim3 grid(T_SEQ / 64, BATCH * NH);  // (32, 32)
        flash_attn_kernel<<<grid, 256, smem>>>(qkv_buf, attn_buf);
    }

    // 3) Output projection: [4096,1024] @ [1024,1024] + b
    {
        dim3 grid(CDIM / 128, M / 128);  // (8, 32)
        sgemm_bias_kernel<<<grid, 256>>>(attn_buf, w_proj, b_proj, out, M, CDIM, CDIM);
    }
}

// round 7
// speedup vs baseline: 1.3894x; 1.3894x over previous
#include <cuda_runtime.h>
#include <cuda_bf16.h>
#include <math.h>
#include <stdint.h>

// Problem constants
#define BATCH   2
#define T_SEQ   2048
#define CDIM    1024
#define NH      16
#define DH      64
#define C3      (3 * CDIM)
#define MROWS   (BATCH * T_SEQ)   // 4096

// ---------------------------------------------------------------------------
// Scratch (device globals — no cudaMalloc allowed)
// ---------------------------------------------------------------------------
__device__ float g_qkv [(size_t)MROWS * C3];     // [B*T, 3C] fp32
__device__ float g_attn[(size_t)MROWS * CDIM];   // [B*T, C]  fp32
__device__ __nv_bfloat16 g_xhi[(size_t)MROWS * CDIM];
__device__ __nv_bfloat16 g_xlo[(size_t)MROWS * CDIM];
__device__ __nv_bfloat16 g_wqkvT_hi[(size_t)C3 * CDIM];   // [3072,1024] (transposed, [N,K])
__device__ __nv_bfloat16 g_wqkvT_lo[(size_t)C3 * CDIM];
__device__ __nv_bfloat16 g_wprojT_hi[(size_t)CDIM * CDIM];
__device__ __nv_bfloat16 g_wprojT_lo[(size_t)CDIM * CDIM];
__device__ __nv_bfloat16 g_ahi[(size_t)MROWS * CDIM];
__device__ __nv_bfloat16 g_alo[(size_t)MROWS * CDIM];

// ---------------------------------------------------------------------------
// PTX helpers (mma.sync / ldmatrix / cp.async — all valid on plain sm_103 target)
// ---------------------------------------------------------------------------
__device__ __forceinline__ uint32_t smem_u32(const void* p) {
    uint32_t a;
    asm("{ .reg .u64 t; cvta.to.shared.u64 t, %1; cvt.u32.u64 %0, t; }" : "=r"(a) : "l"(p));
    return a;
}

#define CP_ASYNC16(dst, src)   asm volatile("cp.async.cg.shared.global [%0], [%1], 16;" :: "r"(dst), "l"(src) : "memory")
#define CP_COMMIT()            asm volatile("cp.async.commit_group;" ::: "memory")
#define CP_WAIT(n)             asm volatile("cp.async.wait_group %0;" :: "n"(n) : "memory")

__device__ __forceinline__ void ldsm_x4(uint32_t* r, uint32_t addr) {
    asm volatile("ldmatrix.sync.aligned.m8n8.x4.shared.b16 {%0,%1,%2,%3}, [%4];"
        : "=r"(r[0]), "=r"(r[1]), "=r"(r[2]), "=r"(r[3]) : "r"(addr));
}

__device__ __forceinline__ void mma_bf16(float* d, const uint32_t* a, const uint32_t* b) {
    asm volatile(
        "mma.sync.aligned.m16n8k16.row.col.f32.bf16.bf16.f32 "
        "{%0,%1,%2,%3}, {%4,%5,%6,%7}, {%8,%9}, {%0,%1,%2,%3};"
        : "+f"(d[0]), "+f"(d[1]), "+f"(d[2]), "+f"(d[3])
        : "r"(a[0]), "r"(a[1]), "r"(a[2]), "r"(a[3]), "r"(b[0]), "r"(b[1]));
}

// ---------------------------------------------------------------------------
// Conversion: fp32 -> bf16 hi/lo (row-major, same layout)
// ---------------------------------------------------------------------------
__global__ void conv_hilo_kernel(const float* __restrict__ in,
                                 __nv_bfloat16* __restrict__ hi,
                                 __nv_bfloat16* __restrict__ lo, int n4) {
    int i = blockIdx.x * blockDim.x + threadIdx.x;
    if (i >= n4) return;
    float4 v = ((const float4*)in)[i];
    __nv_bfloat16 h0 = __float2bfloat16(v.x), h1 = __float2bfloat16(v.y);
    __nv_bfloat16 h2 = __float2bfloat16(v.z), h3 = __float2bfloat16(v.w);
    __nv_bfloat16 l0 = __float2bfloat16(v.x - __bfloat162float(h0));
    __nv_bfloat16 l1 = __float2bfloat16(v.y - __bfloat162float(h1));
    __nv_bfloat16 l2 = __float2bfloat16(v.z - __bfloat162float(h2));
    __nv_bfloat16 l3 = __float2bfloat16(v.w - __bfloat162float(h3));
    __nv_bfloat162* hp = (__nv_bfloat162*)hi;
    __nv_bfloat162* lp = (__nv_bfloat162*)lo;
    hp[2 * i]     = __halves2bfloat162(h0, h1);
    hp[2 * i + 1] = __halves2bfloat162(h2, h3);
    lp[2 * i]     = __halves2bfloat162(l0, l1);
    lp[2 * i + 1] = __halves2bfloat162(l2, l3);
}

// Conversion + transpose: in[K,N] fp32 -> hiT/loT [N,K] bf16
__global__ void convT_hilo_kernel(const float* __restrict__ in,
                                  __nv_bfloat16* __restrict__ hiT,
                                  __nv_bfloat16* __restrict__ loT, int K, int N) {
    __shared__ float t[32][33];
    int nx = blockIdx.x * 32, ky = blockIdx.y * 32;
    int tx = threadIdx.x, ty = threadIdx.y;   // block (32, 8)
#pragma unroll
    for (int i = 0; i < 4; i++)
        t[ty + i * 8][tx] = in[(size_t)(ky + ty + i * 8) * N + nx + tx];
    __syncthreads();
#pragma unroll
    for (int i = 0; i < 4; i++) {
        float v = t[tx][ty + i * 8];
        int n = nx + ty + i * 8, k = ky + tx;
        __nv_bfloat16 h = __float2bfloat16(v);
        hiT[(size_t)n * K + k] = h;
        loT[(size_t)n * K + k] = __float2bfloat16(v - __bfloat162float(h));
    }
}

// ---------------------------------------------------------------------------
// HMMA bf16x3 GEMM: C[M,N] = A[M,K] @ B^T (B given as [N,K]) + bias
// BM=BN=128, BK=32, 256 threads (8 warps, 64x32 warp tiles), cp.async 2-stage.
// smem rows padded to 80B: banks (20r+4c)%32 distinct over 8 rows -> ldmatrix
// conflict-free.
// ---------------------------------------------------------------------------
#define ROWB      80u                 // padded row stride in bytes (32 bf16 = 64B data)
#define OP_BYTES  (128u * ROWB)       // 10240 per operand tile
#define STG_BYTES (4u * OP_BYTES)     // 40960 per stage (Ahi,Alo,Bhi,Blo)
#define GEMM_SMEM (2u * STG_BYTES)    // 81920

__device__ __forceinline__ uint32_t a_frag_addr(uint32_t base, int mr, int ks, int lane) {
    int row = mr + (lane & 7) + ((lane >> 3) & 1) * 8;
    int kb  = ks * 32 + (lane >> 4) * 16;
    return base + row * ROWB + kb;
}
__device__ __forceinline__ uint32_t b_frag_addr(uint32_t base, int nr, int ks, int lane) {
    int row = nr + (lane & 7) + (lane >> 4) * 8;
    int kb  = ks * 32 + ((lane >> 3) & 1) * 16;
    return base + row * ROWB + kb;
}

__global__ __launch_bounds__(256)
void gemm_hmma_bf16x3_kernel(const __nv_bfloat16* __restrict__ Ahi, const __nv_bfloat16* __restrict__ Alo,
                             const __nv_bfloat16* __restrict__ Bhi, const __nv_bfloat16* __restrict__ Blo,
                             const float* __restrict__ bias, float* __restrict__ C,
                             int M, int N, int K) {
    extern __shared__ char smem[];
    const uint32_t sb = smem_u32(smem);
    const int tid = threadIdx.x;
    const int lane = tid & 31;
    const int wid = tid >> 5;
    const int wm = (wid & 1) * 64;      // warp M offset within tile
    const int wn = (wid >> 1) * 32;     // warp N offset within tile
    const int row0 = blockIdx.y * 128, col0 = blockIdx.x * 128;

    const __nv_bfloat16* srcs[4] = {
        Ahi + (size_t)row0 * K, Alo + (size_t)row0 * K,
        Bhi + (size_t)col0 * K, Blo + (size_t)col0 * K };

    // per-thread load coords: 2 positions per operand (512 16B-chunks / 256 thr)
    const int pos0 = tid, pos1 = tid + 256;
    const int r0l = pos0 >> 2, c0l = pos0 & 3;
    const int r1l = pos1 >> 2, c1l = pos1 & 3;

    float acc[4][4][4];
#pragma unroll
    for (int mt = 0; mt < 4; mt++)
#pragma unroll
        for (int nt = 0; nt < 4; nt++)
#pragma unroll
            for (int e = 0; e < 4; e++) acc[mt][nt][e] = 0.f;

    const int nchunk = K / 32;

    // prefetch chunk 0 into stage 0
    {
        uint32_t st = sb;
#pragma unroll
        for (int op = 0; op < 4; op++) {
            const __nv_bfloat16* s = srcs[op];
            CP_ASYNC16(st + op * OP_BYTES + r0l * ROWB + c0l * 16, s + (size_t)r0l * K + c0l * 8);
            CP_ASYNC16(st + op * OP_BYTES + r1l * ROWB + c1l * 16, s + (size_t)r1l * K + c1l * 8);
        }
        CP_COMMIT();
    }

    for (int ch = 0; ch < nchunk; ch++) {
        if (ch + 1 < nchunk) {
            uint32_t st = sb + ((ch + 1) & 1) * STG_BYTES;
            const int k0 = (ch + 1) * 32;
#pragma unroll
            for (int op = 0; op < 4; op++) {
                const __nv_bfloat16* s = srcs[op];
                CP_ASYNC16(st + op * OP_BYTES + r0l * ROWB + c0l * 16, s + (size_t)r0l * K + k0 + c0l * 8);
                CP_ASYNC16(st + op * OP_BYTES + r1l * ROWB + c1l * 16, s + (size_t)r1l * K + k0 + c1l * 8);
            }
            CP_COMMIT();
            CP_WAIT(1);
        } else {
            CP_WAIT(0);
        }
        __syncthreads();

        const uint32_t st = sb + (ch & 1) * STG_BYTES;
        const uint32_t sAhi = st, sAlo = st + OP_BYTES;
        const uint32_t sBhi = st + 2 * OP_BYTES, sBlo = st + 3 * OP_BYTES;

#pragma unroll
        for (int ks = 0; ks < 2; ks++) {
            uint32_t ah[4][4], al[4][4], bh[2][4], bl[2][4];
#pragma unroll
            for (int mt = 0; mt < 4; mt++) {
                ldsm_x4(ah[mt], a_frag_addr(sAhi, wm + 16 * mt, ks, lane));
                ldsm_x4(al[mt], a_frag_addr(sAlo, wm + 16 * mt, ks, lane));
            }
#pragma unroll
            for (int g = 0; g < 2; g++) {
                ldsm_x4(bh[g], b_frag_addr(sBhi, wn + 16 * g, ks, lane));
                ldsm_x4(bl[g], b_frag_addr(sBlo, wn + 16 * g, ks, lane));
            }
#pragma unroll
            for (int mt = 0; mt < 4; mt++) {
#pragma unroll
                for (int g = 0; g < 2; g++) {
                    // ntile 2g uses regs {0,1}; ntile 2g+1 uses regs {2,3}
                    mma_bf16(acc[mt][2 * g],     ah[mt], &bh[g][0]);
                    mma_bf16(acc[mt][2 * g],     ah[mt], &bl[g][0]);
                    mma_bf16(acc[mt][2 * g],     al[mt], &bh[g][0]);
                    mma_bf16(acc[mt][2 * g + 1], ah[mt], &bh[g][2]);
                    mma_bf16(acc[mt][2 * g + 1], ah[mt], &bl[g][2]);
                    mma_bf16(acc[mt][2 * g + 1], al[mt], &bh[g][2]);
                }
            }
        }
        __syncthreads();
    }

    // Epilogue: direct register -> global stores (+bias)
#pragma unroll
    for (int mt = 0; mt < 4; mt++) {
        int r = row0 + wm + 16 * mt + (lane >> 2);
#pragma unroll
        for (int nt = 0; nt < 4; nt++) {
            int c = col0 + wn + 8 * nt + (lane & 3) * 2;
            float bx = __ldg(&bias[c]), by = __ldg(&bias[c + 1]);
            float2 v0 = { acc[mt][nt][0] + bx, acc[mt][nt][1] + by };
            float2 v1 = { acc[mt][nt][2] + bx, acc[mt][nt][3] + by };
            *(float2*)&C[(size_t)r * N + c]       = v0;
            *(float2*)&C[(size_t)(r + 8) * N + c] = v1;
        }
    }
}

// ---------------------------------------------------------------------------
// Flash attention (fp32, causal) — parallel softmax (4 threads/row)
// ---------------------------------------------------------------------------
#define AT_PAD 65

__global__ __launch_bounds__(256, 2)
void flash_attn_kernel(const float* __restrict__ qkv, float* __restrict__ out) {
    extern __shared__ float sm[];
    float* Qs = sm;
    float* Ks = Qs + 64 * AT_PAD;
    float* Vs = Ks + 64 * AT_PAD;
    float* Ps = Vs + 64 * AT_PAD;
    __shared__ float m_s[64], l_s[64], alpha_s[64];

    const int tid = threadIdx.x;
    const int tx = tid & 15;
    const int ty = tid >> 4;
    const int bh = blockIdx.y;
    const int b  = bh >> 4;
    const int h  = bh & 15;
    const int q0 = blockIdx.x * 64;

    const float scale = 0.125f;
    const float* base = qkv + (size_t)b * T_SEQ * C3 + h * DH;

    for (int i = tid; i < 64 * DH; i += 256) {
        int r = i >> 6, d = i & 63;
        Qs[r * AT_PAD + d] = base[(size_t)(q0 + r) * C3 + d] * scale;
    }
    if (tid < 64) { m_s[tid] = -INFINITY; l_s[tid] = 0.f; }

    float o[4][4];
#pragma unroll
    for (int i = 0; i < 4; i++)
#pragma unroll
        for (int j = 0; j < 4; j++) o[i][j] = 0.f;

    const int srow = tid >> 2;            // softmax row (0..63)
    const int spart = tid & 3;            // quarter (16 cols)

    const int ntiles = q0 / 64 + 1;
    for (int kt = 0; kt < ntiles; kt++) {
        const int k0 = kt * 64;
        __syncthreads();
        for (int i = tid; i < 64 * DH; i += 256) {
            int r = i >> 6, d = i & 63;
            size_t gr = (size_t)(k0 + r) * C3;
            Ks[r * AT_PAD + d] = base[gr + CDIM + d];
            Vs[r * AT_PAD + d] = base[gr + 2 * CDIM + d];
        }
        __syncthreads();

        float s[4][4];
#pragma unroll
        for (int i = 0; i < 4; i++)
#pragma unroll
            for (int j = 0; j < 4; j++) s[i][j] = 0.f;
        for (int d = 0; d < DH; d++) {
            float a[4], kk[4];
#pragma unroll
            for (int i = 0; i < 4; i++) a[i] = Qs[(ty * 4 + i) * AT_PAD + d];
#pragma unroll
            for (int j = 0; j < 4; j++) kk[j] = Ks[(tx * 4 + j) * AT_PAD + d];
#pragma unroll
            for (int i = 0; i < 4; i++)
#pragma unroll
                for (int j = 0; j < 4; j++) s[i][j] += a[i] * kk[j];
        }
        if (k0 == q0) {
#pragma unroll
            for (int i = 0; i < 4; i++)
#pragma unroll
                for (int j = 0; j < 4; j++)
                    if (tx * 4 + j > ty * 4 + i) s[i][j] = -INFINITY;
        }
#pragma unroll
        for (int i = 0; i < 4; i++)
#pragma unroll
            for (int j = 0; j < 4; j++)
                Ps[(ty * 4 + i) * AT_PAD + tx * 4 + j] = s[i][j];
        __syncthreads();

        // Parallel online-softmax: 4 threads per row, shfl reduce within quad
        {
            float* prow = &Ps[srow * AT_PAD + spart * 16];
            float mx = -INFINITY;
#pragma unroll
            for (int c = 0; c < 16; c++) mx = fmaxf(mx, prow[c]);
            mx = fmaxf(mx, __shfl_xor_sync(0xffffffffu, mx, 1));
            mx = fmaxf(mx, __shfl_xor_sync(0xffffffffu, mx, 2));
            float m_old = m_s[srow];
            mx = fmaxf(mx, m_old);
            float sum = 0.f;
#pragma unroll
            for (int c = 0; c < 16; c++) {
                float p = __expf(prow[c] - mx);
                prow[c] = p;
                sum += p;
            }
            sum += __shfl_xor_sync(0xffffffffu, sum, 1);
            sum += __shfl_xor_sync(0xffffffffu, sum, 2);
            if (spart == 0) {
                float alpha = __expf(m_old - mx);
                l_s[srow] = l_s[srow] * alpha + sum;
                m_s[srow] = mx;
                alpha_s[srow] = alpha;
            }
        }
        __syncthreads();

        float al[4];
#pragma unroll
        for (int i = 0; i < 4; i++) al[i] = alpha_s[ty * 4 + i];
#pragma unroll
        for (int i = 0; i < 4; i++)
#pragma unroll
            for (int j = 0; j < 4; j++) o[i][j] *= al[i];
        for (int k = 0; k < 64; k++) {
            float p[4], v[4];
#pragma unroll
            for (int i = 0; i < 4; i++) p[i] = Ps[(ty * 4 + i) * AT_PAD + k];
#pragma unroll
            for (int j = 0; j < 4; j++) v[j] = Vs[k * AT_PAD + tx * 4 + j];
#pragma unroll
            for (int i = 0; i < 4; i++)
#pragma unroll
                for (int j = 0; j < 4; j++) o[i][j] += p[i] * v[j];
        }
    }

#pragma unroll
    for (int i = 0; i < 4; i++) {
        float inv = 1.f / l_s[ty * 4 + i];
        size_t row = ((size_t)b * T_SEQ + q0 + ty * 4 + i) * CDIM + h * DH;
#pragma unroll
        for (int j = 0; j < 4; j++)
            out[row + tx * 4 + j] = o[i][j] * inv;
    }
}

// ---------------------------------------------------------------------------
// Launch
// ---------------------------------------------------------------------------
extern "C" void kernel_launch(void* const* d_in, const int* in_sizes, int n_in,
                              void* d_out, int out_size) {
    const float* x      = (const float*)d_in[0];
    const float* w_qkv  = (const float*)d_in[1];
    const float* b_qkv  = (const float*)d_in[2];
    const float* w_proj = (const float*)d_in[3];
    const float* b_proj = (const float*)d_in[4];
    float* out = (float*)d_out;

    float *qkv_buf, *attn_buf;
    __nv_bfloat16 *xhi, *xlo, *wqh, *wql, *wph, *wpl, *ahi, *alo;
    cudaGetSymbolAddress((void**)&qkv_buf, g_qkv);
    cudaGetSymbolAddress((void**)&attn_buf, g_attn);
    cudaGetSymbolAddress((void**)&xhi, g_xhi);
    cudaGetSymbolAddress((void**)&xlo, g_xlo);
    cudaGetSymbolAddress((void**)&wqh, g_wqkvT_hi);
    cudaGetSymbolAddress((void**)&wql, g_wqkvT_lo);
    cudaGetSymbolAddress((void**)&wph, g_wprojT_hi);
    cudaGetSymbolAddress((void**)&wpl, g_wprojT_lo);
    cudaGetSymbolAddress((void**)&ahi, g_ahi);
    cudaGetSymbolAddress((void**)&alo, g_alo);

    const int at_smem = 4 * 64 * AT_PAD * (int)sizeof(float);
    cudaFuncSetAttribute(gemm_hmma_bf16x3_kernel,
                         cudaFuncAttributeMaxDynamicSharedMemorySize, (int)GEMM_SMEM);
    cudaFuncSetAttribute(flash_attn_kernel,
                         cudaFuncAttributeMaxDynamicSharedMemorySize, at_smem);

    // 0) operand conversion
    {
        int n4 = MROWS * CDIM / 4;
        conv_hilo_kernel<<<(n4 + 255) / 256, 256>>>(x, xhi, xlo, n4);
        dim3 blk(32, 8);
        convT_hilo_kernel<<<dim3(C3 / 32, CDIM / 32), blk>>>(w_qkv, wqh, wql, CDIM, C3);
        convT_hilo_kernel<<<dim3(CDIM / 32, CDIM / 32), blk>>>(w_proj, wph, wpl, CDIM, CDIM);
    }

    // 1) QKV projection (HMMA bf16x3): [4096,1024] @ [1024,3072] + b
    gemm_hmma_bf16x3_kernel<<<dim3(C3 / 128, MROWS / 128), 256, GEMM_SMEM>>>(
        xhi, xlo, wqh, wql, b_qkv, qkv_buf, MROWS, C3, CDIM);

    // 2) Flash attention (fp32)
    flash_attn_kernel<<<dim3(T_SEQ / 64, BATCH * NH), 256, at_smem>>>(qkv_buf, attn_buf);

    // 3) convert attention output, then output projection
    {
        int n4 = MROWS * CDIM / 4;
        conv_hilo_kernel<<<(n4 + 255) / 256, 256>>>(attn_buf, ahi, alo, n4);
    }
    gemm_hmma_bf16x3_kernel<<<dim3(CDIM / 128, MROWS / 128), 256, GEMM_SMEM>>>(
        ahi, alo, wph, wpl, b_proj, out, MROWS, CDIM, CDIM);
}

// round 9
// speedup vs baseline: 2.6442x; 1.9032x over previous
#include <cuda_runtime.h>
#include <cuda_bf16.h>
#include <math.h>
#include <stdint.h>

// Problem constants
#define BATCH   2
#define T_SEQ   2048
#define CDIM    1024
#define NH      16
#define DH      64
#define C3      (3 * CDIM)
#define MROWS   (BATCH * T_SEQ)   // 4096

// ---------------------------------------------------------------------------
// Scratch (device globals — no cudaMalloc allowed)
// ---------------------------------------------------------------------------
__device__ __nv_bfloat16 g_qkvhi[(size_t)MROWS * C3];     // [B*T, 3C]
__device__ __nv_bfloat16 g_qkvlo[(size_t)MROWS * C3];
__device__ __nv_bfloat16 g_xhi[(size_t)MROWS * CDIM];
__device__ __nv_bfloat16 g_xlo[(size_t)MROWS * CDIM];
__device__ __nv_bfloat16 g_wqkvT_hi[(size_t)C3 * CDIM];   // [3072,1024] ([N,K])
__device__ __nv_bfloat16 g_wqkvT_lo[(size_t)C3 * CDIM];
__device__ __nv_bfloat16 g_wprojT_hi[(size_t)CDIM * CDIM];
__device__ __nv_bfloat16 g_wprojT_lo[(size_t)CDIM * CDIM];
__device__ __nv_bfloat16 g_ahi[(size_t)MROWS * CDIM];
__device__ __nv_bfloat16 g_alo[(size_t)MROWS * CDIM];

// ---------------------------------------------------------------------------
// PTX helpers
// ---------------------------------------------------------------------------
__device__ __forceinline__ uint32_t smem_u32(const void* p) {
    uint32_t a;
    asm("{ .reg .u64 t; cvta.to.shared.u64 t, %1; cvt.u32.u64 %0, t; }" : "=r"(a) : "l"(p));
    return a;
}

#define CP_ASYNC16(dst, src)   asm volatile("cp.async.cg.shared.global [%0], [%1], 16;" :: "r"(dst), "l"(src) : "memory")
#define CP_COMMIT()            asm volatile("cp.async.commit_group;" ::: "memory")
#define CP_WAIT(n)             asm volatile("cp.async.wait_group %0;" :: "n"(n) : "memory")

__device__ __forceinline__ void ldsm_x4(uint32_t* r, uint32_t addr) {
    asm volatile("ldmatrix.sync.aligned.m8n8.x4.shared.b16 {%0,%1,%2,%3}, [%4];"
        : "=r"(r[0]), "=r"(r[1]), "=r"(r[2]), "=r"(r[3]) : "r"(addr));
}
__device__ __forceinline__ void ldsm_x4_t(uint32_t* r, uint32_t addr) {
    asm volatile("ldmatrix.sync.aligned.m8n8.x4.trans.shared.b16 {%0,%1,%2,%3}, [%4];"
        : "=r"(r[0]), "=r"(r[1]), "=r"(r[2]), "=r"(r[3]) : "r"(addr));
}
__device__ __forceinline__ void mma_bf16(float* d, const uint32_t* a, const uint32_t* b) {
    asm volatile(
        "mma.sync.aligned.m16n8k16.row.col.f32.bf16.bf16.f32 "
        "{%0,%1,%2,%3}, {%4,%5,%6,%7}, {%8,%9}, {%0,%1,%2,%3};"
        : "+f"(d[0]), "+f"(d[1]), "+f"(d[2]), "+f"(d[3])
        : "r"(a[0]), "r"(a[1]), "r"(a[2]), "r"(a[3]), "r"(b[0]), "r"(b[1]));
}

__device__ __forceinline__ uint32_t pack_hi2(float a, float b) {
    __nv_bfloat162 t = __halves2bfloat162(__float2bfloat16(a), __float2bfloat16(b));
    return *(uint32_t*)&t;
}
__device__ __forceinline__ uint32_t pack_lo2(float a, float b) {
    float ra = a - __bfloat162float(__float2bfloat16(a));
    float rb = b - __bfloat162float(__float2bfloat16(b));
    __nv_bfloat162 t = __halves2bfloat162(__float2bfloat16(ra), __float2bfloat16(rb));
    return *(uint32_t*)&t;
}
__device__ __forceinline__ void store_hilo2(__nv_bfloat16* ph, __nv_bfloat16* pl,
                                            float a, float b) {
    __nv_bfloat16 ha = __float2bfloat16(a), hb = __float2bfloat16(b);
    *(__nv_bfloat162*)ph = __halves2bfloat162(ha, hb);
    *(__nv_bfloat162*)pl = __halves2bfloat162(
        __float2bfloat16(a - __bfloat162float(ha)),
        __float2bfloat16(b - __bfloat162float(hb)));
}

// ---------------------------------------------------------------------------
// Conversion kernels
// ---------------------------------------------------------------------------
__global__ void conv_hilo_kernel(const float* __restrict__ in,
                                 __nv_bfloat16* __restrict__ hi,
                                 __nv_bfloat16* __restrict__ lo, int n4) {
    int i = blockIdx.x * blockDim.x + threadIdx.x;
    if (i >= n4) return;
    float4 v = ((const float4*)in)[i];
    uint32_t* hp = (uint32_t*)hi;
    uint32_t* lp = (uint32_t*)lo;
    hp[2 * i]     = pack_hi2(v.x, v.y);
    hp[2 * i + 1] = pack_hi2(v.z, v.w);
    lp[2 * i]     = pack_lo2(v.x, v.y);
    lp[2 * i + 1] = pack_lo2(v.z, v.w);
}

__global__ void convT_hilo_kernel(const float* __restrict__ in,
                                  __nv_bfloat16* __restrict__ hiT,
                                  __nv_bfloat16* __restrict__ loT, int K, int N) {
    __shared__ float t[32][33];
    int nx = blockIdx.x * 32, ky = blockIdx.y * 32;
    int tx = threadIdx.x, ty = threadIdx.y;   // block (32, 8)
#pragma unroll
    for (int i = 0; i < 4; i++)
        t[ty + i * 8][tx] = in[(size_t)(ky + ty + i * 8) * N + nx + tx];
    __syncthreads();
#pragma unroll
    for (int i = 0; i < 4; i++) {
        float v = t[tx][ty + i * 8];
        int n = nx + ty + i * 8, k = ky + tx;
        __nv_bfloat16 h = __float2bfloat16(v);
        hiT[(size_t)n * K + k] = h;
        loT[(size_t)n * K + k] = __float2bfloat16(v - __bfloat162float(h));
    }
}

// ---------------------------------------------------------------------------
// HMMA bf16x3 GEMM: C = A @ B^T + bias (B as [N,K]).
// mode 0: fp32 out -> Cf.  mode 1: hi/lo bf16 out -> Chi/Clo, cols<qcols scaled 0.125.
// ---------------------------------------------------------------------------
#define ROWB      80u
#define OP_BYTES  (128u * ROWB)
#define STG_BYTES (4u * OP_BYTES)
#define GEMM_SMEM (2u * STG_BYTES)    // 81920

__device__ __forceinline__ uint32_t a_frag_addr(uint32_t base, int mr, int ks, int lane) {
    int row = mr + (lane & 7) + ((lane >> 3) & 1) * 8;
    int kb  = ks * 32 + (lane >> 4) * 16;
    return base + row * ROWB + kb;
}
__device__ __forceinline__ uint32_t b_frag_addr(uint32_t base, int nr, int ks, int lane) {
    int row = nr + (lane & 7) + (lane >> 4) * 8;
    int kb  = ks * 32 + ((lane >> 3) & 1) * 16;
    return base + row * ROWB + kb;
}

__global__ __launch_bounds__(256)
void gemm_hmma_bf16x3_kernel(const __nv_bfloat16* __restrict__ Ahi, const __nv_bfloat16* __restrict__ Alo,
                             const __nv_bfloat16* __restrict__ Bhi, const __nv_bfloat16* __restrict__ Blo,
                             const float* __restrict__ bias,
                             float* __restrict__ Cf,
                             __nv_bfloat16* __restrict__ Chi, __nv_bfloat16* __restrict__ Clo,
                             int M, int N, int K, int mode, int qcols) {
    extern __shared__ char smem[];
    const uint32_t sb = smem_u32(smem);
    const int tid = threadIdx.x;
    const int lane = tid & 31;
    const int wid = tid >> 5;
    const int wm = (wid & 1) * 64;
    const int wn = (wid >> 1) * 32;
    const int row0 = blockIdx.y * 128, col0 = blockIdx.x * 128;

    const __nv_bfloat16* srcs[4] = {
        Ahi + (size_t)row0 * K, Alo + (size_t)row0 * K,
        Bhi + (size_t)col0 * K, Blo + (size_t)col0 * K };

    const int pos0 = tid, pos1 = tid + 256;
    const int r0l = pos0 >> 2, c0l = pos0 & 3;
    const int r1l = pos1 >> 2, c1l = pos1 & 3;

    float acc[4][4][4];
#pragma unroll
    for (int mt = 0; mt < 4; mt++)
#pragma unroll
        for (int nt = 0; nt < 4; nt++)
#pragma unroll
            for (int e = 0; e < 4; e++) acc[mt][nt][e] = 0.f;

    const int nchunk = K / 32;
    {
        uint32_t st = sb;
#pragma unroll
        for (int op = 0; op < 4; op++) {
            const __nv_bfloat16* s = srcs[op];
            CP_ASYNC16(st + op * OP_BYTES + r0l * ROWB + c0l * 16, s + (size_t)r0l * K + c0l * 8);
            CP_ASYNC16(st + op * OP_BYTES + r1l * ROWB + c1l * 16, s + (size_t)r1l * K + c1l * 8);
        }
        CP_COMMIT();
    }

    for (int ch = 0; ch < nchunk; ch++) {
        if (ch + 1 < nchunk) {
            uint32_t st = sb + ((ch + 1) & 1) * STG_BYTES;
            const int k0 = (ch + 1) * 32;
#pragma unroll
            for (int op = 0; op < 4; op++) {
                const __nv_bfloat16* s = srcs[op];
                CP_ASYNC16(st + op * OP_BYTES + r0l * ROWB + c0l * 16, s + (size_t)r0l * K + k0 + c0l * 8);
                CP_ASYNC16(st + op * OP_BYTES + r1l * ROWB + c1l * 16, s + (size_t)r1l * K + k0 + c1l * 8);
            }
            CP_COMMIT();
            CP_WAIT(1);
        } else {
            CP_WAIT(0);
        }
        __syncthreads();

        const uint32_t st = sb + (ch & 1) * STG_BYTES;
        const uint32_t sAhi = st, sAlo = st + OP_BYTES;
        const uint32_t sBhi = st + 2 * OP_BYTES, sBlo = st + 3 * OP_BYTES;

#pragma unroll
        for (int ks = 0; ks < 2; ks++) {
            uint32_t ah[4][4], al[4][4], bh[2][4], bl[2][4];
#pragma unroll
            for (int mt = 0; mt < 4; mt++) {
                ldsm_x4(ah[mt], a_frag_addr(sAhi, wm + 16 * mt, ks, lane));
                ldsm_x4(al[mt], a_frag_addr(sAlo, wm + 16 * mt, ks, lane));
            }
#pragma unroll
            for (int g = 0; g < 2; g++) {
                ldsm_x4(bh[g], b_frag_addr(sBhi, wn + 16 * g, ks, lane));
                ldsm_x4(bl[g], b_frag_addr(sBlo, wn + 16 * g, ks, lane));
            }
#pragma unroll
            for (int mt = 0; mt < 4; mt++) {
#pragma unroll
                for (int g = 0; g < 2; g++) {
                    mma_bf16(acc[mt][2 * g],     ah[mt], &bh[g][0]);
                    mma_bf16(acc[mt][2 * g],     ah[mt], &bl[g][0]);
                    mma_bf16(acc[mt][2 * g],     al[mt], &bh[g][0]);
                    mma_bf16(acc[mt][2 * g + 1], ah[mt], &bh[g][2]);
                    mma_bf16(acc[mt][2 * g + 1], ah[mt], &bl[g][2]);
                    mma_bf16(acc[mt][2 * g + 1], al[mt], &bh[g][2]);
                }
            }
        }
        __syncthreads();
    }

#pragma unroll
    for (int mt = 0; mt < 4; mt++) {
        int r = row0 + wm + 16 * mt + (lane >> 2);
#pragma unroll
        for (int nt = 0; nt < 4; nt++) {
            int c = col0 + wn + 8 * nt + (lane & 3) * 2;
            float bx = __ldg(&bias[c]), by = __ldg(&bias[c + 1]);
            float x0 = acc[mt][nt][0] + bx, x1 = acc[mt][nt][1] + by;
            float x2 = acc[mt][nt][2] + bx, x3 = acc[mt][nt][3] + by;
            if (mode == 0) {
                float2 v0 = { x0, x1 }, v1 = { x2, x3 };
                *(float2*)&Cf[(size_t)r * N + c]       = v0;
                *(float2*)&Cf[(size_t)(r + 8) * N + c] = v1;
            } else {
                float sc = (c < qcols) ? 0.125f : 1.f;
                store_hilo2(&Chi[(size_t)r * N + c],       &Clo[(size_t)r * N + c],       x0 * sc, x1 * sc);
                store_hilo2(&Chi[(size_t)(r + 8) * N + c], &Clo[(size_t)(r + 8) * N + c], x2 * sc, x3 * sc);
            }
        }
    }
}

// ---------------------------------------------------------------------------
// HMMA flash attention (causal), bf16x3. Block = 128 queries of one (b,h).
// 8 warps x 16 rows; each warp owns full key/Dh range -> softmax in registers.
// K/V double-buffered via cp.async.
// ---------------------------------------------------------------------------
#define ROWA       144u               // 64 bf16 = 128B data + 16B pad
#define AQ_BYTES   (128u * ROWA)      // 18432
#define AKV_BYTES  (64u * ROWA)       // 9216
#define ATT_SMEM   (2u * AQ_BYTES + 2u * 4u * AKV_BYTES)   // 110592

__device__ __forceinline__ uint32_t afragA(uint32_t base, int mr, int ks, int lane) {
    int row = mr + (lane & 7) + ((lane >> 3) & 1) * 8;
    int kb  = ks * 32 + (lane >> 4) * 16;
    return base + row * ROWA + kb;
}
__device__ __forceinline__ uint32_t bfragA(uint32_t base, int nr, int ks, int lane) {
    int row = nr + (lane & 7) + (lane >> 4) * 8;
    int kb  = ks * 32 + ((lane >> 3) & 1) * 16;
    return base + row * ROWA + kb;
}
// V (trans) fragment: p covers d-cols 16p..16p+15.
// tiles: t0/t1 = d 16p..16p+7 x key {0..7, 8..15}; t2/t3 = d 16p+8..16p+15.
__device__ __forceinline__ uint32_t vfragA(uint32_t base, int ks, int p, int lane) {
    int row = ks * 16 + (lane & 15);
    int col = p * 32 + ((lane >> 4) & 1) * 16;
    return base + row * ROWA + col;
}

__global__ __launch_bounds__(256, 2)
void flash_attn_hmma_kernel(const __nv_bfloat16* __restrict__ qkvhi,
                            const __nv_bfloat16* __restrict__ qkvlo,
                            __nv_bfloat16* __restrict__ ohi,
                            __nv_bfloat16* __restrict__ olo) {
    extern __shared__ char smem[];
    const uint32_t sb = smem_u32(smem);
    const int tid = threadIdx.x, lane = tid & 31, wid = tid >> 5;
    const int bh = blockIdx.y, b = bh >> 4, h = bh & 15;
    const int q0 = blockIdx.x * 128;
    const int wrow = wid * 16;

    const size_t rowbase = (size_t)b * T_SEQ;
    const int qc = h * DH, kc = CDIM + h * DH, vc = 2 * CDIM + h * DH;
    const uint32_t kvb = sb + 2u * AQ_BYTES;

    // Q load (hi+lo): 128 rows x 8 chunks per tensor
#pragma unroll
    for (int t = 0; t < 4; t++) {
        int ci = tid + t * 256;
        int r = ci >> 3, c = ci & 7;
        const size_t grow = (rowbase + q0 + r) * C3 + qc + c * 8;
        CP_ASYNC16(sb + r * ROWA + c * 16,            qkvhi + grow);
        CP_ASYNC16(sb + AQ_BYTES + r * ROWA + c * 16, qkvlo + grow);
    }
    // KV tile 0 into stage 0
    {
        const uint32_t base = kvb;
#pragma unroll
        for (int t = 0; t < 2; t++) {
            int ci = tid + t * 256;
            int r = ci >> 3, c = ci & 7;
            const size_t grow = (rowbase + r) * C3;
            CP_ASYNC16(base + 0 * AKV_BYTES + r * ROWA + c * 16, qkvhi + grow + kc + c * 8);
            CP_ASYNC16(base + 1 * AKV_BYTES + r * ROWA + c * 16, qkvlo + grow + kc + c * 8);
            CP_ASYNC16(base + 2 * AKV_BYTES + r * ROWA + c * 16, qkvhi + grow + vc + c * 8);
            CP_ASYNC16(base + 3 * AKV_BYTES + r * ROWA + c * 16, qkvlo + grow + vc + c * 8);
        }
        CP_COMMIT();
    }

    float m0 = -INFINITY, m1 = -INFINITY, l0 = 0.f, l1 = 0.f;
    float o[8][4];
#pragma unroll
    for (int n = 0; n < 8; n++)
#pragma unroll
        for (int e = 0; e < 4; e++) o[n][e] = 0.f;

    const int ntiles = q0 / 64 + 2;
    for (int kt = 0; kt < ntiles; kt++) {
        __syncthreads();   // all warps done reading the stage we're about to overwrite
        if (kt + 1 < ntiles) {
            const uint32_t base = kvb + ((kt + 1) & 1) * 4u * AKV_BYTES;
            const int k0n = (kt + 1) * 64;
#pragma unroll
            for (int t = 0; t < 2; t++) {
                int ci = tid + t * 256;
                int r = ci >> 3, c = ci & 7;
                const size_t grow = (rowbase + k0n + r) * C3;
                CP_ASYNC16(base + 0 * AKV_BYTES + r * ROWA + c * 16, qkvhi + grow + kc + c * 8);
                CP_ASYNC16(base + 1 * AKV_BYTES + r * ROWA + c * 16, qkvlo + grow + kc + c * 8);
                CP_ASYNC16(base + 2 * AKV_BYTES + r * ROWA + c * 16, qkvhi + grow + vc + c * 8);
                CP_ASYNC16(base + 3 * AKV_BYTES + r * ROWA + c * 16, qkvlo + grow + vc + c * 8);
            }
            CP_COMMIT();
            CP_WAIT(1);
        } else {
            CP_WAIT(0);
        }
        __syncthreads();

        const int k0 = kt * 64;
        const uint32_t stg = kvb + (kt & 1) * 4u * AKV_BYTES;
        const uint32_t sKhi = stg, sKlo = stg + AKV_BYTES;
        const uint32_t sVhi = stg + 2 * AKV_BYTES, sVlo = stg + 3 * AKV_BYTES;

        // ---- S = Q K^T (3-term) ----
        float s[8][4];
#pragma unroll
        for (int n = 0; n < 8; n++)
#pragma unroll
            for (int e = 0; e < 4; e++) s[n][e] = 0.f;

#pragma unroll
        for (int ks = 0; ks < 4; ks++) {
            uint32_t qh[4], ql[4];
            ldsm_x4(qh, afragA(sb, wrow, ks, lane));
            ldsm_x4(ql, afragA(sb + AQ_BYTES, wrow, ks, lane));
#pragma unroll
            for (int g = 0; g < 4; g++) {
                uint32_t kh[4], kl[4];
                ldsm_x4(kh, bfragA(sKhi, g * 16, ks, lane));
                ldsm_x4(kl, bfragA(sKlo, g * 16, ks, lane));
                mma_bf16(s[2 * g],     qh, &kh[0]);
                mma_bf16(s[2 * g],     qh, &kl[0]);
                mma_bf16(s[2 * g],     ql, &kh[0]);
                mma_bf16(s[2 * g + 1], qh, &kh[2]);
                mma_bf16(s[2 * g + 1], qh, &kl[2]);
                mma_bf16(s[2 * g + 1], ql, &kh[2]);
            }
        }

        // ---- causal mask ----
        if (k0 + 63 > q0 + wrow) {
            const int r0g = q0 + wrow + (lane >> 2);
#pragma unroll
            for (int n = 0; n < 8; n++) {
                int cg = k0 + n * 8 + (lane & 3) * 2;
#pragma unroll
                for (int e = 0; e < 4; e++) {
                    int rg = r0g + ((e >> 1) << 3);
                    int cc = cg + (e & 1);
                    if (cc > rg) s[n][e] = -INFINITY;
                }
            }
        }

        // ---- online softmax (per-thread rows, quad reduce) ----
        float mx0 = m0, mx1 = m1;
#pragma unroll
        for (int n = 0; n < 8; n++) {
            mx0 = fmaxf(mx0, fmaxf(s[n][0], s[n][1]));
            mx1 = fmaxf(mx1, fmaxf(s[n][2], s[n][3]));
        }
        mx0 = fmaxf(mx0, __shfl_xor_sync(0xffffffffu, mx0, 1));
        mx0 = fmaxf(mx0, __shfl_xor_sync(0xffffffffu, mx0, 2));
        mx1 = fmaxf(mx1, __shfl_xor_sync(0xffffffffu, mx1, 1));
        mx1 = fmaxf(mx1, __shfl_xor_sync(0xffffffffu, mx1, 2));
        float a0 = __expf(m0 - mx0), a1 = __expf(m1 - mx1);
        m0 = mx0; m1 = mx1;

        float sum0 = 0.f, sum1 = 0.f;
#pragma unroll
        for (int n = 0; n < 8; n++) {
            s[n][0] = __expf(s[n][0] - mx0); sum0 += s[n][0];
            s[n][1] = __expf(s[n][1] - mx0); sum0 += s[n][1];
            s[n][2] = __expf(s[n][2] - mx1); sum1 += s[n][2];
            s[n][3] = __expf(s[n][3] - mx1); sum1 += s[n][3];
        }
        sum0 += __shfl_xor_sync(0xffffffffu, sum0, 1);
        sum0 += __shfl_xor_sync(0xffffffffu, sum0, 2);
        sum1 += __shfl_xor_sync(0xffffffffu, sum1, 1);
        sum1 += __shfl_xor_sync(0xffffffffu, sum1, 2);
        l0 = l0 * a0 + sum0;
        l1 = l1 * a1 + sum1;

#pragma unroll
        for (int n = 0; n < 8; n++) {
            o[n][0] *= a0; o[n][1] *= a0;
            o[n][2] *= a1; o[n][3] *= a1;
        }

        // ---- O += P V (3-term, P split in registers) ----
#pragma unroll
        for (int ks = 0; ks < 4; ks++) {
            uint32_t ph[4], pl[4];
            ph[0] = pack_hi2(s[2 * ks][0],     s[2 * ks][1]);
            ph[1] = pack_hi2(s[2 * ks][2],     s[2 * ks][3]);
            ph[2] = pack_hi2(s[2 * ks + 1][0], s[2 * ks + 1][1]);
            ph[3] = pack_hi2(s[2 * ks + 1][2], s[2 * ks + 1][3]);
            pl[0] = pack_lo2(s[2 * ks][0],     s[2 * ks][1]);
            pl[1] = pack_lo2(s[2 * ks][2],     s[2 * ks][3]);
            pl[2] = pack_lo2(s[2 * ks + 1][0], s[2 * ks + 1][1]);
            pl[3] = pack_lo2(s[2 * ks + 1][2], s[2 * ks + 1][3]);
#pragma unroll
            for (int p = 0; p < 4; p++) {
                uint32_t vh[4], vl[4];
                ldsm_x4_t(vh, vfragA(sVhi, ks, p, lane));
                ldsm_x4_t(vl, vfragA(sVlo, ks, p, lane));
                mma_bf16(o[2 * p],     ph, &vh[0]);
                mma_bf16(o[2 * p],     ph, &vl[0]);
                mma_bf16(o[2 * p],     pl, &vh[0]);
                mma_bf16(o[2 * p + 1], ph, &vh[2]);
                mma_bf16(o[2 * p + 1], ph, &vl[2]);
                mma_bf16(o[2 * p + 1], pl, &vh[2]);
            }
        }
    }

    // ---- epilogue: normalize + hi/lo store ----
    const float inv0 = 1.f / l0, inv1 = 1.f / l1;
    const int r0g = q0 + wrow + (lane >> 2);
    const size_t ro0 = (rowbase + r0g) * CDIM + h * DH;
    const size_t ro1 = (rowbase + r0g + 8) * CDIM + h * DH;
#pragma unroll
    for (int n = 0; n < 8; n++) {
        int c = n * 8 + (lane & 3) * 2;
        store_hilo2(&ohi[ro0 + c], &olo[ro0 + c], o[n][0] * inv0, o[n][1] * inv0);
        store_hilo2(&ohi[ro1 + c], &olo[ro1 + c], o[n][2] * inv1, o[n][3] * inv1);
    }
}

// ---------------------------------------------------------------------------
// Launch
// ---------------------------------------------------------------------------
extern "C" void kernel_launch(void* const* d_in, const int* in_sizes, int n_in,
                              void* d_out, int out_size) {
    const float* x      = (const float*)d_in[0];
    const float* w_qkv  = (const float*)d_in[1];
    const float* b_qkv  = (const float*)d_in[2];
    const float* w_proj = (const float*)d_in[3];
    const float* b_proj = (const float*)d_in[4];
    float* out = (float*)d_out;

    __nv_bfloat16 *qkvhi, *qkvlo, *xhi, *xlo, *wqh, *wql, *wph, *wpl, *ahi, *alo;
    cudaGetSymbolAddress((void**)&qkvhi, g_qkvhi);
    cudaGetSymbolAddress((void**)&qkvlo, g_qkvlo);
    cudaGetSymbolAddress((void**)&xhi, g_xhi);
    cudaGetSymbolAddress((void**)&xlo, g_xlo);
    cudaGetSymbolAddress((void**)&wqh, g_wqkvT_hi);
    cudaGetSymbolAddress((void**)&wql, g_wqkvT_lo);
    cudaGetSymbolAddress((void**)&wph, g_wprojT_hi);
    cudaGetSymbolAddress((void**)&wpl, g_wprojT_lo);
    cudaGetSymbolAddress((void**)&ahi, g_ahi);
    cudaGetSymbolAddress((void**)&alo, g_alo);

    cudaFuncSetAttribute(gemm_hmma_bf16x3_kernel,
                         cudaFuncAttributeMaxDynamicSharedMemorySize, (int)GEMM_SMEM);
    cudaFuncSetAttribute(flash_attn_hmma_kernel,
                         cudaFuncAttributeMaxDynamicSharedMemorySize, (int)ATT_SMEM);

    // 0) operand conversion
    {
        int n4 = MROWS * CDIM / 4;
        conv_hilo_kernel<<<(n4 + 255) / 256, 256>>>(x, xhi, xlo, n4);
        dim3 blk(32, 8);
        convT_hilo_kernel<<<dim3(C3 / 32, CDIM / 32), blk>>>(w_qkv, wqh, wql, CDIM, C3);
        convT_hilo_kernel<<<dim3(CDIM / 32, CDIM / 32), blk>>>(w_proj, wph, wpl, CDIM, CDIM);
    }

    // 1) QKV projection -> bf16 hi/lo (Q pre-scaled by 0.125)
    gemm_hmma_bf16x3_kernel<<<dim3(C3 / 128, MROWS / 128), 256, GEMM_SMEM>>>(
        xhi, xlo, wqh, wql, b_qkv, nullptr, qkvhi, qkvlo, MROWS, C3, CDIM, 1, CDIM);

    // 2) HMMA flash attention -> bf16 hi/lo
    flash_attn_hmma_kernel<<<dim3(T_SEQ / 128, BATCH * NH), 256, ATT_SMEM>>>(
        qkvhi, qkvlo, ahi, alo);

    // 3) Output projection -> fp32 d_out
    gemm_hmma_bf16x3_kernel<<<dim3(CDIM / 128, MROWS / 128), 256, GEMM_SMEM>>>(
        ahi, alo, wph, wpl, b_proj, out, nullptr, nullptr, MROWS, CDIM, CDIM, 0, 0);
}

// round 10
// speedup vs baseline: 2.8926x; 1.0940x over previous
#include <cuda_runtime.h>
#include <cuda_bf16.h>
#include <math.h>
#include <stdint.h>

// Problem constants
#define BATCH   2
#define T_SEQ   2048
#define CDIM    1024
#define NH      16
#define DH      64
#define C3      (3 * CDIM)
#define MROWS   (BATCH * T_SEQ)   // 4096

// ---------------------------------------------------------------------------
// Scratch (device globals — no cudaMalloc allowed)
// ---------------------------------------------------------------------------
__device__ __nv_bfloat16 g_qkvhi[(size_t)MROWS * C3];     // [B*T, 3C]
__device__ __nv_bfloat16 g_qkvlo[(size_t)MROWS * C3];
__device__ __nv_bfloat16 g_xhi[(size_t)MROWS * CDIM];
__device__ __nv_bfloat16 g_xlo[(size_t)MROWS * CDIM];
__device__ __nv_bfloat16 g_wqkvT_hi[(size_t)C3 * CDIM];   // [3072,1024] ([N,K])
__device__ __nv_bfloat16 g_wqkvT_lo[(size_t)C3 * CDIM];
__device__ __nv_bfloat16 g_wprojT_hi[(size_t)CDIM * CDIM];
__device__ __nv_bfloat16 g_wprojT_lo[(size_t)CDIM * CDIM];
__device__ __nv_bfloat16 g_ahi[(size_t)MROWS * CDIM];
__device__ __nv_bfloat16 g_alo[(size_t)MROWS * CDIM];

// ---------------------------------------------------------------------------
// PTX helpers
// ---------------------------------------------------------------------------
__device__ __forceinline__ uint32_t smem_u32(const void* p) {
    uint32_t a;
    asm("{ .reg .u64 t; cvta.to.shared.u64 t, %1; cvt.u32.u64 %0, t; }" : "=r"(a) : "l"(p));
    return a;
}

#define CP_ASYNC16(dst, src)   asm volatile("cp.async.cg.shared.global [%0], [%1], 16;" :: "r"(dst), "l"(src) : "memory")
#define CP_COMMIT()            asm volatile("cp.async.commit_group;" ::: "memory")
#define CP_WAIT(n)             asm volatile("cp.async.wait_group %0;" :: "n"(n) : "memory")

__device__ __forceinline__ void ldsm_x4(uint32_t* r, uint32_t addr) {
    asm volatile("ldmatrix.sync.aligned.m8n8.x4.shared.b16 {%0,%1,%2,%3}, [%4];"
        : "=r"(r[0]), "=r"(r[1]), "=r"(r[2]), "=r"(r[3]) : "r"(addr));
}
__device__ __forceinline__ void ldsm_x4_t(uint32_t* r, uint32_t addr) {
    asm volatile("ldmatrix.sync.aligned.m8n8.x4.trans.shared.b16 {%0,%1,%2,%3}, [%4];"
        : "=r"(r[0]), "=r"(r[1]), "=r"(r[2]), "=r"(r[3]) : "r"(addr));
}
__device__ __forceinline__ void mma_bf16(float* d, const uint32_t* a, const uint32_t* b) {
    asm volatile(
        "mma.sync.aligned.m16n8k16.row.col.f32.bf16.bf16.f32 "
        "{%0,%1,%2,%3}, {%4,%5,%6,%7}, {%8,%9}, {%0,%1,%2,%3};"
        : "+f"(d[0]), "+f"(d[1]), "+f"(d[2]), "+f"(d[3])
        : "r"(a[0]), "r"(a[1]), "r"(a[2]), "r"(a[3]), "r"(b[0]), "r"(b[1]));
}

__device__ __forceinline__ uint32_t pack_hi2(float a, float b) {
    __nv_bfloat162 t = __halves2bfloat162(__float2bfloat16(a), __float2bfloat16(b));
    return *(uint32_t*)&t;
}
__device__ __forceinline__ uint32_t pack_lo2(float a, float b) {
    float ra = a - __bfloat162float(__float2bfloat16(a));
    float rb = b - __bfloat162float(__float2bfloat16(b));
    __nv_bfloat162 t = __halves2bfloat162(__float2bfloat16(ra), __float2bfloat16(rb));
    return *(uint32_t*)&t;
}
__device__ __forceinline__ void store_hilo2(__nv_bfloat16* ph, __nv_bfloat16* pl,
                                            float a, float b) {
    __nv_bfloat16 ha = __float2bfloat16(a), hb = __float2bfloat16(b);
    *(__nv_bfloat162*)ph = __halves2bfloat162(ha, hb);
    *(__nv_bfloat162*)pl = __halves2bfloat162(
        __float2bfloat16(a - __bfloat162float(ha)),
        __float2bfloat16(b - __bfloat162float(hb)));
}

// ---------------------------------------------------------------------------
// Conversion kernels
// ---------------------------------------------------------------------------
__global__ void conv_hilo_kernel(const float* __restrict__ in,
                                 __nv_bfloat16* __restrict__ hi,
                                 __nv_bfloat16* __restrict__ lo, int n4) {
    int i = blockIdx.x * blockDim.x + threadIdx.x;
    if (i >= n4) return;
    float4 v = ((const float4*)in)[i];
    uint32_t* hp = (uint32_t*)hi;
    uint32_t* lp = (uint32_t*)lo;
    hp[2 * i]     = pack_hi2(v.x, v.y);
    hp[2 * i + 1] = pack_hi2(v.z, v.w);
    lp[2 * i]     = pack_lo2(v.x, v.y);
    lp[2 * i + 1] = pack_lo2(v.z, v.w);
}

__global__ void convT_hilo_kernel(const float* __restrict__ in,
                                  __nv_bfloat16* __restrict__ hiT,
                                  __nv_bfloat16* __restrict__ loT, int K, int N) {
    __shared__ float t[32][33];
    int nx = blockIdx.x * 32, ky = blockIdx.y * 32;
    int tx = threadIdx.x, ty = threadIdx.y;   // block (32, 8)
#pragma unroll
    for (int i = 0; i < 4; i++)
        t[ty + i * 8][tx] = in[(size_t)(ky + ty + i * 8) * N + nx + tx];
    __syncthreads();
#pragma unroll
    for (int i = 0; i < 4; i++) {
        float v = t[tx][ty + i * 8];
        int n = nx + ty + i * 8, k = ky + tx;
        __nv_bfloat16 h = __float2bfloat16(v);
        hiT[(size_t)n * K + k] = h;
        loT[(size_t)n * K + k] = __float2bfloat16(v - __bfloat162float(h));
    }
}

// ---------------------------------------------------------------------------
// HMMA bf16x3 GEMM: C = A @ B^T + bias (B as [N,K]).
// mode 0: fp32 out -> Cf.  mode 1: hi/lo bf16 out -> Chi/Clo, cols<qcols scaled 0.125.
// __launch_bounds__(256, 2): clamp regs to 128 so 2 CTAs/SM are resident.
// ---------------------------------------------------------------------------
#define ROWB      80u
#define OP_BYTES  (128u * ROWB)
#define STG_BYTES (4u * OP_BYTES)
#define GEMM_SMEM (2u * STG_BYTES)    // 81920  (2 CTAs -> 160KB of 227KB)

__device__ __forceinline__ uint32_t a_frag_addr(uint32_t base, int mr, int ks, int lane) {
    int row = mr + (lane & 7) + ((lane >> 3) & 1) * 8;
    int kb  = ks * 32 + (lane >> 4) * 16;
    return base + row * ROWB + kb;
}
__device__ __forceinline__ uint32_t b_frag_addr(uint32_t base, int nr, int ks, int lane) {
    int row = nr + (lane & 7) + (lane >> 4) * 8;
    int kb  = ks * 32 + ((lane >> 3) & 1) * 16;
    return base + row * ROWB + kb;
}

__global__ __launch_bounds__(256, 2)
void gemm_hmma_bf16x3_kernel(const __nv_bfloat16* __restrict__ Ahi, const __nv_bfloat16* __restrict__ Alo,
                             const __nv_bfloat16* __restrict__ Bhi, const __nv_bfloat16* __restrict__ Blo,
                             const float* __restrict__ bias,
                             float* __restrict__ Cf,
                             __nv_bfloat16* __restrict__ Chi, __nv_bfloat16* __restrict__ Clo,
                             int M, int N, int K, int mode, int qcols) {
    extern __shared__ char smem[];
    const uint32_t sb = smem_u32(smem);
    const int tid = threadIdx.x;
    const int lane = tid & 31;
    const int wid = tid >> 5;
    const int wm = (wid & 1) * 64;
    const int wn = (wid >> 1) * 32;
    const int row0 = blockIdx.y * 128, col0 = blockIdx.x * 128;

    const __nv_bfloat16* srcs[4] = {
        Ahi + (size_t)row0 * K, Alo + (size_t)row0 * K,
        Bhi + (size_t)col0 * K, Blo + (size_t)col0 * K };

    const int pos0 = tid, pos1 = tid + 256;
    const int r0l = pos0 >> 2, c0l = pos0 & 3;
    const int r1l = pos1 >> 2, c1l = pos1 & 3;

    float acc[4][4][4];
#pragma unroll
    for (int mt = 0; mt < 4; mt++)
#pragma unroll
        for (int nt = 0; nt < 4; nt++)
#pragma unroll
            for (int e = 0; e < 4; e++) acc[mt][nt][e] = 0.f;

    const int nchunk = K / 32;
    {
        uint32_t st = sb;
#pragma unroll
        for (int op = 0; op < 4; op++) {
            const __nv_bfloat16* s = srcs[op];
            CP_ASYNC16(st + op * OP_BYTES + r0l * ROWB + c0l * 16, s + (size_t)r0l * K + c0l * 8);
            CP_ASYNC16(st + op * OP_BYTES + r1l * ROWB + c1l * 16, s + (size_t)r1l * K + c1l * 8);
        }
        CP_COMMIT();
    }

    for (int ch = 0; ch < nchunk; ch++) {
        if (ch + 1 < nchunk) {
            uint32_t st = sb + ((ch + 1) & 1) * STG_BYTES;
            const int k0 = (ch + 1) * 32;
#pragma unroll
            for (int op = 0; op < 4; op++) {
                const __nv_bfloat16* s = srcs[op];
                CP_ASYNC16(st + op * OP_BYTES + r0l * ROWB + c0l * 16, s + (size_t)r0l * K + k0 + c0l * 8);
                CP_ASYNC16(st + op * OP_BYTES + r1l * ROWB + c1l * 16, s + (size_t)r1l * K + k0 + c1l * 8);
            }
            CP_COMMIT();
            CP_WAIT(1);
        } else {
            CP_WAIT(0);
        }
        __syncthreads();

        const uint32_t st = sb + (ch & 1) * STG_BYTES;
        const uint32_t sAhi = st, sAlo = st + OP_BYTES;
        const uint32_t sBhi = st + 2 * OP_BYTES, sBlo = st + 3 * OP_BYTES;

#pragma unroll
        for (int ks = 0; ks < 2; ks++) {
            uint32_t ah[4][4], al[4][4], bh[2][4], bl[2][4];
#pragma unroll
            for (int mt = 0; mt < 4; mt++) {
                ldsm_x4(ah[mt], a_frag_addr(sAhi, wm + 16 * mt, ks, lane));
                ldsm_x4(al[mt], a_frag_addr(sAlo, wm + 16 * mt, ks, lane));
            }
#pragma unroll
            for (int g = 0; g < 2; g++) {
                ldsm_x4(bh[g], b_frag_addr(sBhi, wn + 16 * g, ks, lane));
                ldsm_x4(bl[g], b_frag_addr(sBlo, wn + 16 * g, ks, lane));
            }
#pragma unroll
            for (int mt = 0; mt < 4; mt++) {
#pragma unroll
                for (int g = 0; g < 2; g++) {
                    mma_bf16(acc[mt][2 * g],     ah[mt], &bh[g][0]);
                    mma_bf16(acc[mt][2 * g],     ah[mt], &bl[g][0]);
                    mma_bf16(acc[mt][2 * g],     al[mt], &bh[g][0]);
                    mma_bf16(acc[mt][2 * g + 1], ah[mt], &bh[g][2]);
                    mma_bf16(acc[mt][2 * g + 1], ah[mt], &bl[g][2]);
                    mma_bf16(acc[mt][2 * g + 1], al[mt], &bh[g][2]);
                }
            }
        }
        __syncthreads();
    }

#pragma unroll
    for (int mt = 0; mt < 4; mt++) {
        int r = row0 + wm + 16 * mt + (lane >> 2);
#pragma unroll
        for (int nt = 0; nt < 4; nt++) {
            int c = col0 + wn + 8 * nt + (lane & 3) * 2;
            float bx = __ldg(&bias[c]), by = __ldg(&bias[c + 1]);
            float x0 = acc[mt][nt][0] + bx, x1 = acc[mt][nt][1] + by;
            float x2 = acc[mt][nt][2] + bx, x3 = acc[mt][nt][3] + by;
            if (mode == 0) {
                float2 v0 = { x0, x1 }, v1 = { x2, x3 };
                *(float2*)&Cf[(size_t)r * N + c]       = v0;
                *(float2*)&Cf[(size_t)(r + 8) * N + c] = v1;
            } else {
                float sc = (c < qcols) ? 0.125f : 1.f;
                store_hilo2(&Chi[(size_t)r * N + c],       &Clo[(size_t)r * N + c],       x0 * sc, x1 * sc);
                store_hilo2(&Chi[(size_t)(r + 8) * N + c], &Clo[(size_t)(r + 8) * N + c], x2 * sc, x3 * sc);
            }
        }
    }
}

// ---------------------------------------------------------------------------
// HMMA flash attention (causal), bf16x3. Block = 128 queries of one (b,h).
// 8 warps x 16 rows; each warp owns full key/Dh range -> softmax in registers.
// K/V double-buffered via cp.async.
// ---------------------------------------------------------------------------
#define ROWA       144u               // 64 bf16 = 128B data + 16B pad
#define AQ_BYTES   (128u * ROWA)      // 18432
#define AKV_BYTES  (64u * ROWA)       // 9216
#define ATT_SMEM   (2u * AQ_BYTES + 2u * 4u * AKV_BYTES)   // 110592

__device__ __forceinline__ uint32_t afragA(uint32_t base, int mr, int ks, int lane) {
    int row = mr + (lane & 7) + ((lane >> 3) & 1) * 8;
    int kb  = ks * 32 + (lane >> 4) * 16;
    return base + row * ROWA + kb;
}
__device__ __forceinline__ uint32_t bfragA(uint32_t base, int nr, int ks, int lane) {
    int row = nr + (lane & 7) + (lane >> 4) * 8;
    int kb  = ks * 32 + ((lane >> 3) & 1) * 16;
    return base + row * ROWA + kb;
}
// V (trans) fragment: p covers d-cols 16p..16p+15.
// tiles: t0/t1 = d 16p..16p+7 x key {0..7, 8..15}; t2/t3 = d 16p+8..16p+15.
__device__ __forceinline__ uint32_t vfragA(uint32_t base, int ks, int p, int lane) {
    int row = ks * 16 + (lane & 15);
    int col = p * 32 + ((lane >> 4) & 1) * 16;
    return base + row * ROWA + col;
}

__global__ __launch_bounds__(256, 2)
void flash_attn_hmma_kernel(const __nv_bfloat16* __restrict__ qkvhi,
                            const __nv_bfloat16* __restrict__ qkvlo,
                            __nv_bfloat16* __restrict__ ohi,
                            __nv_bfloat16* __restrict__ olo) {
    extern __shared__ char smem[];
    const uint32_t sb = smem_u32(smem);
    const int tid = threadIdx.x, lane = tid & 31, wid = tid >> 5;
    const int bh = blockIdx.y, b = bh >> 4, h = bh & 15;
    const int q0 = blockIdx.x * 128;
    const int wrow = wid * 16;

    const size_t rowbase = (size_t)b * T_SEQ;
    const int qc = h * DH, kc = CDIM + h * DH, vc = 2 * CDIM + h * DH;
    const uint32_t kvb = sb + 2u * AQ_BYTES;

    // Q load (hi+lo): 128 rows x 8 chunks per tensor
#pragma unroll
    for (int t = 0; t < 4; t++) {
        int ci = tid + t * 256;
        int r = ci >> 3, c = ci & 7;
        const size_t grow = (rowbase + q0 + r) * C3 + qc + c * 8;
        CP_ASYNC16(sb + r * ROWA + c * 16,            qkvhi + grow);
        CP_ASYNC16(sb + AQ_BYTES + r * ROWA + c * 16, qkvlo + grow);
    }
    // KV tile 0 into stage 0
    {
        const uint32_t base = kvb;
#pragma unroll
        for (int t = 0; t < 2; t++) {
            int ci = tid + t * 256;
            int r = ci >> 3, c = ci & 7;
            const size_t grow = (rowbase + r) * C3;
            CP_ASYNC16(base + 0 * AKV_BYTES + r * ROWA + c * 16, qkvhi + grow + kc + c * 8);
            CP_ASYNC16(base + 1 * AKV_BYTES + r * ROWA + c * 16, qkvlo + grow + kc + c * 8);
            CP_ASYNC16(base + 2 * AKV_BYTES + r * ROWA + c * 16, qkvhi + grow + vc + c * 8);
            CP_ASYNC16(base + 3 * AKV_BYTES + r * ROWA + c * 16, qkvlo + grow + vc + c * 8);
        }
        CP_COMMIT();
    }

    float m0 = -INFINITY, m1 = -INFINITY, l0 = 0.f, l1 = 0.f;
    float o[8][4];
#pragma unroll
    for (int n = 0; n < 8; n++)
#pragma unroll
        for (int e = 0; e < 4; e++) o[n][e] = 0.f;

    const int ntiles = q0 / 64 + 2;
    for (int kt = 0; kt < ntiles; kt++) {
        __syncthreads();   // all warps done reading the stage we're about to overwrite
        if (kt + 1 < ntiles) {
            const uint32_t base = kvb + ((kt + 1) & 1) * 4u * AKV_BYTES;
            const int k0n = (kt + 1) * 64;
#pragma unroll
            for (int t = 0; t < 2; t++) {
                int ci = tid + t * 256;
                int r = ci >> 3, c = ci & 7;
                const size_t grow = (rowbase + k0n + r) * C3;
                CP_ASYNC16(base + 0 * AKV_BYTES + r * ROWA + c * 16, qkvhi + grow + kc + c * 8);
                CP_ASYNC16(base + 1 * AKV_BYTES + r * ROWA + c * 16, qkvlo + grow + kc + c * 8);
                CP_ASYNC16(base + 2 * AKV_BYTES + r * ROWA + c * 16, qkvhi + grow + vc + c * 8);
                CP_ASYNC16(base + 3 * AKV_BYTES + r * ROWA + c * 16, qkvlo + grow + vc + c * 8);
            }
            CP_COMMIT();
            CP_WAIT(1);
        } else {
            CP_WAIT(0);
        }
        __syncthreads();

        const int k0 = kt * 64;
        const uint32_t stg = kvb + (kt & 1) * 4u * AKV_BYTES;
        const uint32_t sKhi = stg, sKlo = stg + AKV_BYTES;
        const uint32_t sVhi = stg + 2 * AKV_BYTES, sVlo = stg + 3 * AKV_BYTES;

        // ---- S = Q K^T (3-term) ----
        float s[8][4];
#pragma unroll
        for (int n = 0; n < 8; n++)
#pragma unroll
            for (int e = 0; e < 4; e++) s[n][e] = 0.f;

#pragma unroll
        for (int ks = 0; ks < 4; ks++) {
            uint32_t qh[4], ql[4];
            ldsm_x4(qh, afragA(sb, wrow, ks, lane));
            ldsm_x4(ql, afragA(sb + AQ_BYTES, wrow, ks, lane));
#pragma unroll
            for (int g = 0; g < 4; g++) {
                uint32_t kh[4], kl[4];
                ldsm_x4(kh, bfragA(sKhi, g * 16, ks, lane));
                ldsm_x4(kl, bfragA(sKlo, g * 16, ks, lane));
                mma_bf16(s[2 * g],     qh, &kh[0]);
                mma_bf16(s[2 * g],     qh, &kl[0]);
                mma_bf16(s[2 * g],     ql, &kh[0]);
                mma_bf16(s[2 * g + 1], qh, &kh[2]);
                mma_bf16(s[2 * g + 1], qh, &kl[2]);
                mma_bf16(s[2 * g + 1], ql, &kh[2]);
            }
        }

        // ---- causal mask ----
        if (k0 + 63 > q0 + wrow) {
            const int r0g = q0 + wrow + (lane >> 2);
#pragma unroll
            for (int n = 0; n < 8; n++) {
                int cg = k0 + n * 8 + (lane & 3) * 2;
#pragma unroll
                for (int e = 0; e < 4; e++) {
                    int rg = r0g + ((e >> 1) << 3);
                    int cc = cg + (e & 1);
                    if (cc > rg) s[n][e] = -INFINITY;
                }
            }
        }

        // ---- online softmax (per-thread rows, quad reduce) ----
        float mx0 = m0, mx1 = m1;
#pragma unroll
        for (int n = 0; n < 8; n++) {
            mx0 = fmaxf(mx0, fmaxf(s[n][0], s[n][1]));
            mx1 = fmaxf(mx1, fmaxf(s[n][2], s[n][3]));
        }
        mx0 = fmaxf(mx0, __shfl_xor_sync(0xffffffffu, mx0, 1));
        mx0 = fmaxf(mx0, __shfl_xor_sync(0xffffffffu, mx0, 2));
        mx1 = fmaxf(mx1, __shfl_xor_sync(0xffffffffu, mx1, 1));
        mx1 = fmaxf(mx1, __shfl_xor_sync(0xffffffffu, mx1, 2));
        float a0 = __expf(m0 - mx0), a1 = __expf(m1 - mx1);
        m0 = mx0; m1 = mx1;

        float sum0 = 0.f, sum1 = 0.f;
#pragma unroll
        for (int n = 0; n < 8; n++) {
            s[n][0] = __expf(s[n][0] - mx0); sum0 += s[n][0];
            s[n][1] = __expf(s[n][1] - mx0); sum0 += s[n][1];
            s[n][2] = __expf(s[n][2] - mx1); sum1 += s[n][2];
            s[n][3] = __expf(s[n][3] - mx1); sum1 += s[n][3];
        }
        sum0 += __shfl_xor_sync(0xffffffffu, sum0, 1);
        sum0 += __shfl_xor_sync(0xffffffffu, sum0, 2);
        sum1 += __shfl_xor_sync(0xffffffffu, sum1, 1);
        sum1 += __shfl_xor_sync(0xffffffffu, sum1, 2);
        l0 = l0 * a0 + sum0;
        l1 = l1 * a1 + sum1;

#pragma unroll
        for (int n = 0; n < 8; n++) {
            o[n][0] *= a0; o[n][1] *= a0;
            o[n][2] *= a1; o[n][3] *= a1;
        }

        // ---- O += P V (3-term, P split in registers) ----
#pragma unroll
        for (int ks = 0; ks < 4; ks++) {
            uint32_t ph[4], pl[4];
            ph[0] = pack_hi2(s[2 * ks][0],     s[2 * ks][1]);
            ph[1] = pack_hi2(s[2 * ks][2],     s[2 * ks][3]);
            ph[2] = pack_hi2(s[2 * ks + 1][0], s[2 * ks + 1][1]);
            ph[3] = pack_hi2(s[2 * ks + 1][2], s[2 * ks + 1][3]);
            pl[0] = pack_lo2(s[2 * ks][0],     s[2 * ks][1]);
            pl[1] = pack_lo2(s[2 * ks][2],     s[2 * ks][3]);
            pl[2] = pack_lo2(s[2 * ks + 1][0], s[2 * ks + 1][1]);
            pl[3] = pack_lo2(s[2 * ks + 1][2], s[2 * ks + 1][3]);
#pragma unroll
            for (int p = 0; p < 4; p++) {
                uint32_t vh[4], vl[4];
                ldsm_x4_t(vh, vfragA(sVhi, ks, p, lane));
                ldsm_x4_t(vl, vfragA(sVlo, ks, p, lane));
                mma_bf16(o[2 * p],     ph, &vh[0]);
                mma_bf16(o[2 * p],     ph, &vl[0]);
                mma_bf16(o[2 * p],     pl, &vh[0]);
                mma_bf16(o[2 * p + 1], ph, &vh[2]);
                mma_bf16(o[2 * p + 1], ph, &vl[2]);
                mma_bf16(o[2 * p + 1], pl, &vh[2]);
            }
        }
    }

    // ---- epilogue: normalize + hi/lo store ----
    const float inv0 = 1.f / l0, inv1 = 1.f / l1;
    const int r0g = q0 + wrow + (lane >> 2);
    const size_t ro0 = (rowbase + r0g) * CDIM + h * DH;
    const size_t ro1 = (rowbase + r0g + 8) * CDIM + h * DH;
#pragma unroll
    for (int n = 0; n < 8; n++) {
        int c = n * 8 + (lane & 3) * 2;
        store_hilo2(&ohi[ro0 + c], &olo[ro0 + c], o[n][0] * inv0, o[n][1] * inv0);
        store_hilo2(&ohi[ro1 + c], &olo[ro1 + c], o[n][2] * inv1, o[n][3] * inv1);
    }
}

// ---------------------------------------------------------------------------
// Launch
// ---------------------------------------------------------------------------
extern "C" void kernel_launch(void* const* d_in, const int* in_sizes, int n_in,
                              void* d_out, int out_size) {
    const float* x      = (const float*)d_in[0];
    const float* w_qkv  = (const float*)d_in[1];
    const float* b_qkv  = (const float*)d_in[2];
    const float* w_proj = (const float*)d_in[3];
    const float* b_proj = (const float*)d_in[4];
    float* out = (float*)d_out;

    __nv_bfloat16 *qkvhi, *qkvlo, *xhi, *xlo, *wqh, *wql, *wph, *wpl, *ahi, *alo;
    cudaGetSymbolAddress((void**)&qkvhi, g_qkvhi);
    cudaGetSymbolAddress((void**)&qkvlo, g_qkvlo);
    cudaGetSymbolAddress((void**)&xhi, g_xhi);
    cudaGetSymbolAddress((void**)&xlo, g_xlo);
    cudaGetSymbolAddress((void**)&wqh, g_wqkvT_hi);
    cudaGetSymbolAddress((void**)&wql, g_wqkvT_lo);
    cudaGetSymbolAddress((void**)&wph, g_wprojT_hi);
    cudaGetSymbolAddress((void**)&wpl, g_wprojT_lo);
    cudaGetSymbolAddress((void**)&ahi, g_ahi);
    cudaGetSymbolAddress((void**)&alo, g_alo);

    cudaFuncSetAttribute(gemm_hmma_bf16x3_kernel,
                         cudaFuncAttributeMaxDynamicSharedMemorySize, (int)GEMM_SMEM);
    cudaFuncSetAttribute(flash_attn_hmma_kernel,
                         cudaFuncAttributeMaxDynamicSharedMemorySize, (int)ATT_SMEM);

    // 0) operand conversion
    {
        int n4 = MROWS * CDIM / 4;
        conv_hilo_kernel<<<(n4 + 255) / 256, 256>>>(x, xhi, xlo, n4);
        dim3 blk(32, 8);
        convT_hilo_kernel<<<dim3(C3 / 32, CDIM / 32), blk>>>(w_qkv, wqh, wql, CDIM, C3);
        convT_hilo_kernel<<<dim3(CDIM / 32, CDIM / 32), blk>>>(w_proj, wph, wpl, CDIM, CDIM);
    }

    // 1) QKV projection -> bf16 hi/lo (Q pre-scaled by 0.125)
    gemm_hmma_bf16x3_kernel<<<dim3(C3 / 128, MROWS / 128), 256, GEMM_SMEM>>>(
        xhi, xlo, wqh, wql, b_qkv, nullptr, qkvhi, qkvlo, MROWS, C3, CDIM, 1, CDIM);

    // 2) HMMA flash attention -> bf16 hi/lo
    flash_attn_hmma_kernel<<<dim3(T_SEQ / 128, BATCH * NH), 256, ATT_SMEM>>>(
        qkvhi, qkvlo, ahi, alo);

    // 3) Output projection -> fp32 d_out
    gemm_hmma_bf16x3_kernel<<<dim3(CDIM / 128, MROWS / 128), 256, GEMM_SMEM>>>(
        ahi, alo, wph, wpl, b_proj, out, nullptr, nullptr, MROWS, CDIM, CDIM, 0, 0);
}